// round 15
// baseline (speedup 1.0000x reference)
#include <cuda_runtime.h>
#include <cuda_fp8.h>
#include <cstdint>
#include <cstddef>

// Problem dims (fixed)
#define MDIM 16384
#define KDIM 4096
#define NDIM 4096

// ---------------- device globals ----------------
__device__ unsigned int g_amax_x;
__device__ unsigned int g_amax_w;
__device__ __align__(16) unsigned char g_xq[67108864];   // [M,K] fp8 e4m3, K-major
__device__ __align__(16) unsigned char g_wq[16777216];   // [N,K] fp8 e4m3, K-major (w^T)

// ---------------- GEMM config ----------------
#define BM 128
#define BN 256
#define KC 128
#define STAGES 3
#define ITERS (KDIM / KC)        // 32
#define A_BYTES (BM * 128)       // 16384
#define B_BYTES (BN * 128)       // 32768
#define STAGE_BYTES (A_BYTES + B_BYTES)     // 49152
#define SMEM_BYTES (STAGES * STAGE_BYTES)   // 147456

// ---------------- helpers ----------------
__device__ __forceinline__ uint32_t smem_u32(const void* p) {
    uint32_t a;
    asm("{ .reg .u64 t; cvta.to.shared.u64 t, %1; cvt.u32.u64 %0, t; }" : "=r"(a) : "l"(p));
    return a;
}
__device__ __forceinline__ void cp_async16(uint32_t sdst, const void* gsrc) {
    asm volatile("cp.async.cg.shared.global [%0], [%1], 16;" :: "r"(sdst), "l"(gsrc) : "memory");
}
__device__ __forceinline__ void ldsm4(uint32_t& r0, uint32_t& r1, uint32_t& r2, uint32_t& r3,
                                      uint32_t addr) {
    asm volatile("ldmatrix.sync.aligned.m8n8.x4.shared.b16 {%0,%1,%2,%3}, [%4];"
                 : "=r"(r0), "=r"(r1), "=r"(r2), "=r"(r3) : "r"(addr));
}
__device__ __forceinline__ void mma_fp8(float& c0, float& c1, float& c2, float& c3,
                                        uint32_t a0, uint32_t a1, uint32_t a2, uint32_t a3,
                                        uint32_t b0, uint32_t b1) {
    asm volatile(
        "mma.sync.aligned.m16n8k32.row.col.f32.e4m3.e4m3.f32 "
        "{%0,%1,%2,%3}, {%4,%5,%6,%7}, {%8,%9}, {%0,%1,%2,%3};"
        : "+f"(c0), "+f"(c1), "+f"(c2), "+f"(c3)
        : "r"(a0), "r"(a1), "r"(a2), "r"(a3), "r"(b0), "r"(b1));
}
__device__ __forceinline__ uint32_t swz(uint32_t off) {
    return off ^ ((off >> 3) & 0x70u);
}

// Load one stage: A tile 128x128B + B tile 256x128B, 16B cp.async chunks, 256 threads.
__device__ __forceinline__ void load_stage(uint32_t sbase, const unsigned char* Ag,
                                           const unsigned char* Bg, int tid) {
    #pragma unroll
    for (int it = 0; it < 12; it++) {
        int c = tid + it * 256;            // 0..3071
        int isB = (c >= 1024);             // A = 1024 chunks, B = 2048 chunks
        int cc = isB ? (c - 1024) : c;
        int row = cc >> 3;
        int chunk = cc & 7;
        uint32_t off = (uint32_t)(row * 128 + chunk * 16);
        uint32_t dst = sbase + (uint32_t)(isB ? A_BYTES : 0) + swz(off);
        const unsigned char* src = (isB ? Bg : Ag) + (size_t)row * KDIM + chunk * 16;
        cp_async16(dst, src);
    }
}

// ---------------- GEMM kernel ----------------
__global__ void __launch_bounds__(256, 1) gemm_kernel(float* __restrict__ out) {
    extern __shared__ __align__(16) unsigned char smem[];
    const uint32_t sb = smem_u32(smem);
    const int tid = threadIdx.x;
    const int wid = tid >> 5;
    const int lid = tid & 31;
    const int wm = wid >> 2;       // 0..1 -> 64-row slice
    const int wn = wid & 3;        // 0..3 -> 64-col slice
    const int n0 = blockIdx.x * BN;
    const int m0 = blockIdx.y * BM;

    const unsigned char* Ag = g_xq + (size_t)m0 * KDIM;
    const unsigned char* Bg = g_wq + (size_t)n0 * KDIM;

    float acc[4][8][4];            // [mf 16-row][nf 8-col][frag]
    #pragma unroll
    for (int mf = 0; mf < 4; mf++)
        #pragma unroll
        for (int nf = 0; nf < 8; nf++)
            #pragma unroll
            for (int j = 0; j < 4; j++) acc[mf][nf][j] = 0.0f;

    // ldmatrix lane mappings (validated in R5)
    const int a_row_in = lid & 15;
    const int a_ci = lid >> 4;                       // 0/1 -> which 16B half of k32
    const int b_row_in = ((lid >> 4) << 3) + (lid & 7);
    const int b_ci = (lid >> 3) & 1;

    // double-buffered fragments
    uint32_t a[2][4][4];
    uint32_t b[2][8][2];

    #define LOAD_FRAGS(buf, kk_) do {                                                   \
        _Pragma("unroll")                                                               \
        for (int mf = 0; mf < 4; mf++) {                                                \
            const uint32_t off = (uint32_t)((wm * 64 + mf * 16 + a_row_in) * 128        \
                                            + ((kk_) * 2 + a_ci) * 16);                 \
            ldsm4(a[buf][mf][0], a[buf][mf][1], a[buf][mf][2], a[buf][mf][3],           \
                  sA + swz(off));                                                       \
        }                                                                               \
        _Pragma("unroll")                                                               \
        for (int nf2 = 0; nf2 < 4; nf2++) {                                             \
            const uint32_t off = (uint32_t)((wn * 64 + nf2 * 16 + b_row_in) * 128       \
                                            + ((kk_) * 2 + b_ci) * 16);                 \
            uint32_t r0, r1, r2, r3;                                                    \
            ldsm4(r0, r1, r2, r3, sB + swz(off));                                       \
            b[buf][nf2 * 2 + 0][0] = r0; b[buf][nf2 * 2 + 0][1] = r1;                   \
            b[buf][nf2 * 2 + 1][0] = r2; b[buf][nf2 * 2 + 1][1] = r3;                   \
        }                                                                               \
    } while (0)

    // prologue: fill first STAGES-1 stages
    #pragma unroll
    for (int s = 0; s < STAGES - 1; s++) {
        load_stage(sb + s * STAGE_BYTES, Ag + s * KC, Bg + s * KC, tid);
        asm volatile("cp.async.commit_group;" ::: "memory");
    }

    for (int i = 0; i < ITERS; i++) {
        if (i + STAGES - 1 < ITERS) {
            const int ls = (i + STAGES - 1) % STAGES;
            load_stage(sb + ls * STAGE_BYTES,
                       Ag + (size_t)(i + STAGES - 1) * KC,
                       Bg + (size_t)(i + STAGES - 1) * KC, tid);
            asm volatile("cp.async.commit_group;" ::: "memory");
            asm volatile("cp.async.wait_group %0;" :: "n"(STAGES - 1) : "memory");
        } else {
            asm volatile("cp.async.wait_group 0;" ::: "memory");
        }
        __syncthreads();

        const uint32_t sA = sb + (uint32_t)((i % STAGES) * STAGE_BYTES);
        const uint32_t sB = sA + A_BYTES;

        LOAD_FRAGS(0, 0);
        #pragma unroll
        for (int kk = 0; kk < 4; kk++) {
            const int cur = kk & 1;
            if (kk < 3) {
                const int nxt = cur ^ 1;
                LOAD_FRAGS(nxt, kk + 1);
            }
            #pragma unroll
            for (int mf = 0; mf < 4; mf++)
                #pragma unroll
                for (int nf = 0; nf < 8; nf++)
                    mma_fp8(acc[mf][nf][0], acc[mf][nf][1], acc[mf][nf][2], acc[mf][nf][3],
                            a[cur][mf][0], a[cur][mf][1], a[cur][mf][2], a[cur][mf][3],
                            b[cur][nf][0], b[cur][nf][1]);
        }
        __syncthreads();
    }
    #undef LOAD_FRAGS

    // epilogue: dequantize and store
    const float sc = __uint_as_float(g_amax_x) * __uint_as_float(g_amax_w)
                     * (1.0f / (448.0f * 448.0f));
    const int lrow = lid >> 2;
    const int lq = lid & 3;
    #pragma unroll
    for (int mf = 0; mf < 4; mf++) {
        #pragma unroll
        for (int nf = 0; nf < 8; nf++) {
            const int m = m0 + wm * 64 + mf * 16 + lrow;
            const int n = n0 + wn * 64 + nf * 8 + lq * 2;
            float2 v0 = make_float2(acc[mf][nf][0] * sc, acc[mf][nf][1] * sc);
            float2 v1 = make_float2(acc[mf][nf][2] * sc, acc[mf][nf][3] * sc);
            *reinterpret_cast<float2*>(out + (size_t)m * NDIM + n) = v0;
            *reinterpret_cast<float2*>(out + (size_t)(m + 8) * NDIM + n) = v1;
        }
    }
}

// ---------------- pre-pass kernels ----------------
__global__ void reset_kernel() {
    g_amax_x = 0u;
    g_amax_w = 0u;
}

__global__ void absmax_kernel(const float4* __restrict__ p, long n4, int which) {
    float m = 0.0f;
    const long stride = (long)gridDim.x * blockDim.x;
    for (long i = (long)blockIdx.x * blockDim.x + threadIdx.x; i < n4; i += stride) {
        float4 v = p[i];
        m = fmaxf(m, fmaxf(fmaxf(fabsf(v.x), fabsf(v.y)), fmaxf(fabsf(v.z), fabsf(v.w))));
    }
    #pragma unroll
    for (int o = 16; o > 0; o >>= 1) m = fmaxf(m, __shfl_xor_sync(0xFFFFFFFFu, m, o));
    if ((threadIdx.x & 31) == 0) {
        atomicMax(which ? &g_amax_w : &g_amax_x, __float_as_uint(m));
    }
}

__device__ __forceinline__ unsigned char q8(float v) {
    return (unsigned char)__nv_cvt_float_to_fp8(v, __NV_SATFINITE, __NV_E4M3);
}

// quantize x (scale computed inline from g_amax_x)
__global__ void quant_x_kernel(const float4* __restrict__ x, long n4) {
    const float sx = 448.0f / __uint_as_float(g_amax_x);
    uint32_t* __restrict__ outw = reinterpret_cast<uint32_t*>(g_xq);
    const long stride = (long)gridDim.x * blockDim.x;
    for (long i = (long)blockIdx.x * blockDim.x + threadIdx.x; i < n4; i += stride) {
        float4 v = x[i];
        uint32_t o = (uint32_t)q8(v.x * sx)
                   | ((uint32_t)q8(v.y * sx) << 8)
                   | ((uint32_t)q8(v.z * sx) << 16)
                   | ((uint32_t)q8(v.w * sx) << 24);
        outw[i] = o;
    }
}

// quantize + transpose w: wq[n*K + k] = q(w[k*N + n] * sw)
__global__ void quant_w_kernel(const float* __restrict__ w) {
    __shared__ unsigned char t[32][33];
    const int n0 = blockIdx.x * 32;
    const int k0 = blockIdx.y * 32;
    const float sw = 448.0f / __uint_as_float(g_amax_w);
    const int tx = threadIdx.x;  // 0..31
    const int ty = threadIdx.y;  // 0..7
    #pragma unroll
    for (int i = 0; i < 4; i++) {
        const int kk = ty + i * 8;
        const float v = w[(size_t)(k0 + kk) * NDIM + n0 + tx];
        t[kk][tx] = q8(v * sw);
    }
    __syncthreads();
    #pragma unroll
    for (int i = 0; i < 4; i++) {
        const int nn = ty + i * 8;
        g_wq[(size_t)(n0 + nn) * KDIM + k0 + tx] = t[tx][nn];
    }
}

// ---------------- launcher ----------------
extern "C" void kernel_launch(void* const* d_in, const int* in_sizes, int n_in,
                              void* d_out, int out_size) {
    const float* x = (const float*)d_in[0];   // [M,K]
    const float* w = (const float*)d_in[1];   // [K,N]
    float* out = (float*)d_out;               // [M,N]

    // launch indices 0..5 — GEMM is #5 so ncu (-s 5 -c 1) profiles it
    reset_kernel<<<1, 1>>>();
    absmax_kernel<<<2048, 256>>>((const float4*)x, (long)MDIM * KDIM / 4, 0);
    absmax_kernel<<<1024, 256>>>((const float4*)w, (long)KDIM * NDIM / 4, 1);
    quant_x_kernel<<<4096, 256>>>((const float4*)x, (long)MDIM * KDIM / 4);
    quant_w_kernel<<<dim3(NDIM / 32, KDIM / 32), dim3(32, 8)>>>(w);

    cudaFuncSetAttribute(gemm_kernel, cudaFuncAttributeMaxDynamicSharedMemorySize, SMEM_BYTES);
    gemm_kernel<<<dim3(NDIM / BN, MDIM / BM), 256, SMEM_BYTES>>>(out);
}